// round 15
// baseline (speedup 1.0000x reference)
#include <cuda_runtime.h>
#include <cuda_bf16.h>
#include <float.h>

#define NN 100000
#define NE 1600000
#define DIM 32
#define NEG_SLOPE 0.2f
#define CSR_BLOCKS 148
#define CSR_THREADS 1024

// -------- static device scratch (16B aligned for float4 access) --------
// Invariant: g_deg == 0 at every kernel_launch entry (zero at module load,
// re-zeroed by k_attn each call). Barrier cnt returns to 0 after each use.
__device__ int      g_deg[NN];
__device__ int      g_cursor[NN];
__device__ int      g_rowptr[NN + 1];
__device__ int      g_partial[CSR_BLOCKS];
__device__ unsigned g_bar_cnt = 0;
__device__ unsigned g_bar_gen = 0;
__device__ int      g_csrc[NE];                    // src ids grouped by dst (CSR)
__device__ float    g_Dinv[NN];
__device__ __align__(16) float g_A[NN * DIM];      // pass1: u*Dinv; later: X2
__device__ __align__(16) float g_A2[NN * DIM];     // pass-2 agg input (X1*Dinv)
__device__ __align__(16) float g_X1[NN * DIM];
__device__ __align__(16) float g_FS[NN * DIM];     // fsrc
__device__ __align__(16) float g_FD[NN * DIM];     // fdst

// Sense-reversing grid barrier (all CSR_BLOCKS co-resident: 148 <= 152 SMs).
__device__ __forceinline__ void grid_bar() {
    __syncthreads();
    if (threadIdx.x == 0) {
        __threadfence();
        unsigned gen = *(volatile unsigned*)&g_bar_gen;
        unsigned a = atomicAdd(&g_bar_cnt, 1u);
        if (a == gridDim.x - 1) {
            *(volatile unsigned*)&g_bar_cnt = 0;
            __threadfence();
            atomicAdd(&g_bar_gen, 1u);            // release
        } else {
            while (*(volatile unsigned*)&g_bar_gen == gen) __nanosleep(64);
        }
        __threadfence();
    }
    __syncthreads();
}

// Block-wide exclusive scan over 1024 threads. Returns (exclusive, total).
__device__ __forceinline__ int2 block_scan(int v, int* swarp) {
    int lane = threadIdx.x & 31, w5 = threadIdx.x >> 5;
    int x = v;
#pragma unroll
    for (int off = 1; off < 32; off <<= 1) {
        int y = __shfl_up_sync(0xffffffffu, x, off);
        if (lane >= off) x += y;
    }
    if (lane == 31) swarp[w5] = x;
    __syncthreads();
    if (w5 == 0) {
        int s = swarp[lane];
#pragma unroll
        for (int off = 1; off < 32; off <<= 1) {
            int y = __shfl_up_sync(0xffffffffu, s, off);
            if (lane >= off) s += y;
        }
        swarp[lane] = s;
    }
    __syncthreads();
    int incl = x + (w5 > 0 ? swarp[w5 - 1] : 0);
    int total = swarp[31];
    __syncthreads();                               // protect smem reuse
    return make_int2(incl - v, total);
}

// Persistent: histogram -> scan -> rowptr/cursor/Dinv -> A = u*Dinv.
__global__ __launch_bounds__(CSR_THREADS, 1)
void k_histscan(const float* __restrict__ u, const int* __restrict__ edst,
                int n, int e) {
    __shared__ int swarp[32];
    int tid = threadIdx.x, bid = blockIdx.x;
    int gt = bid * CSR_THREADS + tid;
    int gsz = gridDim.x * CSR_THREADS;

    for (int i = gt; i < e; i += gsz)
        atomicAdd(&g_deg[edst[i]], 1);
    grid_bar();

    int node = gt;
    int v = (node < n) ? g_deg[node] : 0;
    int2 sc = block_scan(v, swarp);
    if (tid == 0) g_partial[bid] = sc.y;
    grid_bar();

    if (bid == 0) {
        int vv = (tid < CSR_BLOCKS) ? g_partial[tid] : 0;
        int2 sc2 = block_scan(vv, swarp);
        if (tid < CSR_BLOCKS) g_partial[tid] = sc2.x;
        if (tid == CSR_BLOCKS - 1) g_rowptr[n] = sc2.x + vv;   // grand total
    }
    grid_bar();

    if (node < n) {
        int off = g_partial[bid] + sc.x;
        g_rowptr[node] = off;
        g_cursor[node] = off;
        float dg = (float)v;
        g_Dinv[node] = rsqrtf(dg < 1.0f ? 1.0f : dg);
    }
    grid_bar();

    const float4* u4 = (const float4*)u;
    float4* A4 = (float4*)g_A;
    int n8 = n * 8;
    for (int j = gt; j < n8; j += gsz) {
        float d = g_Dinv[j >> 3];
        float4 vv = u4[j];
        vv.x *= d; vv.y *= d; vv.z *= d; vv.w *= d;
        A4[j] = vv;
    }
}

// Full-grid scatter: max TLP for the 1.6M atomics + scattered stores.
__global__ void k_scatter(const int* __restrict__ esrc, const int* __restrict__ edst, int e) {
    int i = blockIdx.x * blockDim.x + threadIdx.x;
    if (i < e) {
        int p = atomicAdd(&g_cursor[edst[i]], 1);
        g_csrc[p] = esrc[i];
    }
}

// agg pass 1 fused with cheb1. Warp per node; 4 groups of 8 lanes, group =
// edge. Plain counted loop — measured 33us (R8/R12).
__global__ void k_aggcheb(const float* __restrict__ u, const float* __restrict__ lam, int n) {
    int w = (blockIdx.x * blockDim.x + threadIdx.x) >> 5;
    int lane = threadIdx.x & 31;
    if (w >= n) return;
    int grp = lane >> 3, sub = lane & 7;
    int s0 = g_rowptr[w], s1 = g_rowptr[w + 1];
    const float4* A4 = (const float4*)g_A;
    float4 acc = make_float4(0.f, 0.f, 0.f, 0.f);
    for (int e = s0 + grp; e < s1; e += 4) {
        int sid = g_csrc[e];
        float4 v = A4[sid * 8 + sub];
        acc.x += v.x; acc.y += v.y; acc.z += v.z; acc.w += v.w;
    }
#pragma unroll
    for (int off = 8; off <= 16; off <<= 1) {
        acc.x += __shfl_xor_sync(0xffffffffu, acc.x, off);
        acc.y += __shfl_xor_sync(0xffffffffu, acc.y, off);
        acc.z += __shfl_xor_sync(0xffffffffu, acc.z, off);
        acc.w += __shfl_xor_sync(0xffffffffu, acc.w, off);
    }
    if (grp == 0) {
        float d = g_Dinv[w];
        float r = 2.0f / lam[0];
        float4 uv = ((const float4*)u)[w * 8 + sub];
        float4 x1;
        x1.x = -r * (acc.x * d) + (r - 1.0f) * uv.x;
        x1.y = -r * (acc.y * d) + (r - 1.0f) * uv.y;
        x1.z = -r * (acc.z * d) + (r - 1.0f) * uv.z;
        x1.w = -r * (acc.w * d) + (r - 1.0f) * uv.w;
        ((float4*)g_X1)[w * 8 + sub] = x1;
        float4 a; a.x = x1.x * d; a.y = x1.y * d; a.z = x1.z * d; a.w = x1.w * d;
        ((float4*)g_A2)[w * 8 + sub] = a;
    }
}

// agg pass 2 (same validated shape as k_aggcheb): gathers g_A2, epilogue
// computes X2 and stores it into g_A (free after pass 1; no intra-launch
// hazard: reads only g_A2, writes only g_A).
__global__ void k_agg2(const float* __restrict__ u, const float* __restrict__ lam, int n) {
    int w = (blockIdx.x * blockDim.x + threadIdx.x) >> 5;
    int lane = threadIdx.x & 31;
    if (w >= n) return;
    int grp = lane >> 3, sub = lane & 7;
    int s0 = g_rowptr[w], s1 = g_rowptr[w + 1];
    const float4* A4 = (const float4*)g_A2;
    float4 acc = make_float4(0.f, 0.f, 0.f, 0.f);
    for (int e = s0 + grp; e < s1; e += 4) {
        int sid = g_csrc[e];
        float4 v = A4[sid * 8 + sub];
        acc.x += v.x; acc.y += v.y; acc.z += v.z; acc.w += v.w;
    }
#pragma unroll
    for (int off = 8; off <= 16; off <<= 1) {
        acc.x += __shfl_xor_sync(0xffffffffu, acc.x, off);
        acc.y += __shfl_xor_sync(0xffffffffu, acc.y, off);
        acc.z += __shfl_xor_sync(0xffffffffu, acc.z, off);
        acc.w += __shfl_xor_sync(0xffffffffu, acc.w, off);
    }
    if (grp == 0) {
        float d = g_Dinv[w];
        float r = 2.0f / lam[0];
        float4 uv = ((const float4*)u)[w * 8 + sub];
        float4 x1 = ((const float4*)g_X1)[w * 8 + sub];
        float4 x2;
        x2.x = -2.0f * r * (acc.x * d) + 2.0f * (r - 1.0f) * x1.x - uv.x;
        x2.y = -2.0f * r * (acc.y * d) + 2.0f * (r - 1.0f) * x1.y - uv.y;
        x2.z = -2.0f * r * (acc.z * d) + 2.0f * (r - 1.0f) * x1.z - uv.z;
        x2.w = -2.0f * r * (acc.w * d) + 2.0f * (r - 1.0f) * x1.w - uv.w;
        ((float4*)g_A)[w * 8 + sub] = x2;
    }
}

// Pure node GEMM: hc = relu([X0|X1|X2]@Wc+bc); FS = hc@Ws+bs; FD = hc@Wd+bd.
// 256-thd blocks, 8 nodes/block — regs/smem allow ~5 blocks/SM (vs the 147us
// R13 monolith at 1 block/SM).
__global__ void k_node(const float* __restrict__ u,
                       const float* __restrict__ Wc, const float* __restrict__ bc,
                       const float* __restrict__ Ws, const float* __restrict__ bs,
                       const float* __restrict__ Wd, const float* __restrict__ bd,
                       int n) {
    __shared__ __align__(16) float sW1t[32 * 100];
    __shared__ __align__(16) float sW2t[32 * 36];
    __shared__ __align__(16) float sW3t[32 * 36];
    __shared__ float sb1[32], sb2[32], sb3[32];
    __shared__ __align__(16) float xsh[8][96];
    __shared__ __align__(16) float hcsh[8][32];

    int tid = threadIdx.x;
    for (int i = tid; i < 96 * 32; i += 256) {
        int j = i >> 5, d = i & 31;
        sW1t[d * 100 + j] = Wc[i];
    }
    for (int i = tid; i < 32 * 32; i += 256) {
        int j = i >> 5, d = i & 31;
        sW2t[d * 36 + j] = Ws[i];
        sW3t[d * 36 + j] = Wd[i];
    }
    if (tid < 32) { sb1[tid] = bc[tid]; sb2[tid] = bs[tid]; sb3[tid] = bd[tid]; }
    __syncthreads();

    int wid = tid >> 5, lane = tid & 31;
    int node = blockIdx.x * 8 + wid;
    if (node >= n) return;

    xsh[wid][lane]      = u[node * DIM + lane];
    xsh[wid][32 + lane] = g_X1[node * DIM + lane];
    xsh[wid][64 + lane] = g_A[node * DIM + lane];      // X2
    __syncwarp();

    float acc1 = sb1[lane];
    const float4* xr = (const float4*)&xsh[wid][0];
    const float4* w1 = (const float4*)&sW1t[lane * 100];
#pragma unroll
    for (int j4 = 0; j4 < 24; j4++) {
        float4 xv = xr[j4];
        float4 wv = w1[j4];
        acc1 += xv.x * wv.x + xv.y * wv.y + xv.z * wv.z + xv.w * wv.w;
    }
    float hc = fmaxf(acc1, 0.0f);
    hcsh[wid][lane] = hc;
    __syncwarp();

    float fs = sb2[lane], fd = sb3[lane];
    const float4* hr = (const float4*)&hcsh[wid][0];
    const float4* w2 = (const float4*)&sW2t[lane * 36];
    const float4* w3 = (const float4*)&sW3t[lane * 36];
#pragma unroll
    for (int j4 = 0; j4 < 8; j4++) {
        float4 hv = hr[j4];
        float4 a2 = w2[j4];
        float4 a3 = w3[j4];
        fs += hv.x * a2.x + hv.y * a2.y + hv.z * a2.z + hv.w * a2.w;
        fd += hv.x * a3.x + hv.y * a3.y + hv.z * a3.z + hv.w * a3.w;
    }
    g_FS[node * DIM + lane] = fs;
    g_FD[node * DIM + lane] = fd;
}

// GATv2 fused edge softmax + aggregation (no max subtraction; logits bounded
// ~13). Group-mask shuffles in the divergent loop; full mask after. Re-zeroes
// g_deg for the next call.
__global__ __launch_bounds__(256, 7)
void k_attn(float* __restrict__ out, const float* __restrict__ attn, int n) {
    int gid = blockIdx.x * blockDim.x + threadIdx.x;
    if (gid < NN) g_deg[gid] = 0;          // restore call-entry invariant
    int w = gid >> 5;
    int lane = threadIdx.x & 31;
    if (w >= n) return;
    int grp = lane >> 3, sub = lane & 7;
    unsigned gmask = 0xffu << (grp * 8);
    int s0 = g_rowptr[w], s1 = g_rowptr[w + 1];
    const float4* FS4 = (const float4*)g_FS;
    float4 a4 = ((const float4*)attn)[sub];
    float4 fd4 = ((const float4*)g_FD)[w * 8 + sub];

    float den = 0.0f;
    float4 acc = make_float4(0.f, 0.f, 0.f, 0.f);

    for (int e = s0 + grp; e < s1; e += 4) {
        int sid = g_csrc[e];
        float4 v = FS4[sid * 8 + sub];
        float4 t;
        t.x = v.x + fd4.x; t.y = v.y + fd4.y; t.z = v.z + fd4.z; t.w = v.w + fd4.w;
        t.x = (t.x > 0.f) ? t.x : NEG_SLOPE * t.x;
        t.y = (t.y > 0.f) ? t.y : NEG_SLOPE * t.y;
        t.z = (t.z > 0.f) ? t.z : NEG_SLOPE * t.z;
        t.w = (t.w > 0.f) ? t.w : NEG_SLOPE * t.w;
        float l = t.x * a4.x + t.y * a4.y + t.z * a4.z + t.w * a4.w;
#pragma unroll
        for (int off = 1; off <= 4; off <<= 1)
            l += __shfl_xor_sync(gmask, l, off);   // group-local, converged
        float p = __expf(l);
        den += p;
        acc.x += p * v.x; acc.y += p * v.y; acc.z += p * v.z; acc.w += p * v.w;
    }

#pragma unroll
    for (int off = 8; off <= 16; off <<= 1) {
        den   += __shfl_xor_sync(0xffffffffu, den, off);
        acc.x += __shfl_xor_sync(0xffffffffu, acc.x, off);
        acc.y += __shfl_xor_sync(0xffffffffu, acc.y, off);
        acc.z += __shfl_xor_sync(0xffffffffu, acc.z, off);
        acc.w += __shfl_xor_sync(0xffffffffu, acc.w, off);
    }

    if (grp == 0) {
        float4 o;
        if (den > 0.0f) {
            float inv = 1.0f / den;
            o.x = acc.x * inv; o.y = acc.y * inv; o.z = acc.z * inv; o.w = acc.w * inv;
        } else {
            o = make_float4(0.f, 0.f, 0.f, 0.f);
        }
        ((float4*)out)[w * 8 + sub] = o;
    }
}

// ---------------------------------------------------------------------
extern "C" void kernel_launch(void* const* d_in, const int* in_sizes, int n_in,
                              void* d_out, int out_size) {
    const float* u     = (const float*)d_in[0];
    const float* lam   = (const float*)d_in[1];
    const int*   esrc  = (const int*)d_in[2];
    const int*   edst  = (const int*)d_in[3];
    const float* chebW = (const float*)d_in[4];
    const float* chebb = (const float*)d_in[5];
    const float* srcW  = (const float*)d_in[6];
    const float* srcb  = (const float*)d_in[7];
    const float* dstW  = (const float*)d_in[8];
    const float* dstb  = (const float*)d_in[9];
    const float* attn  = (const float*)d_in[10];
    float* out = (float*)d_out;

    int N = in_sizes[0] / DIM;
    int E = in_sizes[2];

    int tb = 256;
    int gE = (E + tb - 1) / tb;
    int gWarp = (N * 32 + tb - 1) / tb;
    int gNode8 = (N + 7) / 8;

    k_histscan<<<CSR_BLOCKS, CSR_THREADS>>>(u, edst, N, E);   // 0
    k_scatter<<<gE, tb>>>(esrc, edst, E);                     // 1
    k_aggcheb<<<gWarp, tb>>>(u, lam, N);                      // 2
    k_agg2<<<gWarp, tb>>>(u, lam, N);                         // 3  <- ncu lands here
    k_node<<<gNode8, tb>>>(u, chebW, chebb,
                           srcW, srcb, dstW, dstb, N);        // 4
    k_attn<<<gWarp, tb>>>(out, attn, N);                      // 5
}

// round 16
// speedup vs baseline: 1.0492x; 1.0492x over previous
#include <cuda_runtime.h>
#include <cuda_bf16.h>
#include <float.h>

#define NN 100000
#define NE 1600000
#define DIM 32
#define NEG_SLOPE 0.2f
#define LOG2E 1.44269504f
#define CSR_BLOCKS 148
#define CSR_THREADS 1024

// -------- static device scratch (16B aligned for float4 access) --------
// Invariant: g_deg == 0 at every kernel_launch entry (zero at module load,
// re-zeroed by k_attn each call). Barrier cnt returns to 0 after each use.
__device__ int      g_deg[NN];
__device__ int      g_cursor[NN];
__device__ int      g_rowptr[NN + 1];
__device__ int      g_partial[CSR_BLOCKS];
__device__ unsigned g_bar_cnt = 0;
__device__ unsigned g_bar_gen = 0;
__device__ int      g_csrc[NE];                    // src ids grouped by dst (CSR)
__device__ float    g_Dinv[NN];
__device__ __align__(16) float g_A[NN * DIM];      // pass-1 agg input (u*Dinv)
__device__ __align__(16) float g_A2[NN * DIM];     // pass-2 agg input (X1*Dinv)
__device__ __align__(16) float g_X1[NN * DIM];
__device__ __align__(16) float g_FS[NN * DIM];     // fsrc
__device__ __align__(16) float g_FD[NN * DIM];     // fdst

// Sense-reversing grid barrier (all CSR_BLOCKS co-resident: 148 <= 152 SMs).
__device__ __forceinline__ void grid_bar() {
    __syncthreads();
    if (threadIdx.x == 0) {
        __threadfence();
        unsigned gen = *(volatile unsigned*)&g_bar_gen;
        unsigned a = atomicAdd(&g_bar_cnt, 1u);
        if (a == gridDim.x - 1) {
            *(volatile unsigned*)&g_bar_cnt = 0;
            __threadfence();
            atomicAdd(&g_bar_gen, 1u);            // release
        } else {
            while (*(volatile unsigned*)&g_bar_gen == gen) __nanosleep(64);
        }
        __threadfence();
    }
    __syncthreads();
}

// Block-wide exclusive scan over 1024 threads. Returns (exclusive, total).
__device__ __forceinline__ int2 block_scan(int v, int* swarp) {
    int lane = threadIdx.x & 31, w5 = threadIdx.x >> 5;
    int x = v;
#pragma unroll
    for (int off = 1; off < 32; off <<= 1) {
        int y = __shfl_up_sync(0xffffffffu, x, off);
        if (lane >= off) x += y;
    }
    if (lane == 31) swarp[w5] = x;
    __syncthreads();
    if (w5 == 0) {
        int s = swarp[lane];
#pragma unroll
        for (int off = 1; off < 32; off <<= 1) {
            int y = __shfl_up_sync(0xffffffffu, s, off);
            if (lane >= off) s += y;
        }
        swarp[lane] = s;
    }
    __syncthreads();
    int incl = x + (w5 > 0 ? swarp[w5 - 1] : 0);
    int total = swarp[31];
    __syncthreads();                               // protect smem reuse
    return make_int2(incl - v, total);
}

// Persistent: histogram -> scan -> rowptr/cursor/Dinv -> A = u*Dinv.
__global__ __launch_bounds__(CSR_THREADS, 1)
void k_histscan(const float* __restrict__ u, const int* __restrict__ edst,
                int n, int e) {
    __shared__ int swarp[32];
    int tid = threadIdx.x, bid = blockIdx.x;
    int gt = bid * CSR_THREADS + tid;
    int gsz = gridDim.x * CSR_THREADS;

    for (int i = gt; i < e; i += gsz)
        atomicAdd(&g_deg[edst[i]], 1);
    grid_bar();

    int node = gt;
    int v = (node < n) ? g_deg[node] : 0;
    int2 sc = block_scan(v, swarp);
    if (tid == 0) g_partial[bid] = sc.y;
    grid_bar();

    if (bid == 0) {
        int vv = (tid < CSR_BLOCKS) ? g_partial[tid] : 0;
        int2 sc2 = block_scan(vv, swarp);
        if (tid < CSR_BLOCKS) g_partial[tid] = sc2.x;
        if (tid == CSR_BLOCKS - 1) g_rowptr[n] = sc2.x + vv;   // grand total
    }
    grid_bar();

    if (node < n) {
        int off = g_partial[bid] + sc.x;
        g_rowptr[node] = off;
        g_cursor[node] = off;
        float dg = (float)v;
        g_Dinv[node] = rsqrtf(dg < 1.0f ? 1.0f : dg);
    }
    grid_bar();

    const float4* u4 = (const float4*)u;
    float4* A4 = (float4*)g_A;
    int n8 = n * 8;
    for (int j = gt; j < n8; j += gsz) {
        float d = g_Dinv[j >> 3];
        float4 vv = u4[j];
        vv.x *= d; vv.y *= d; vv.z *= d; vv.w *= d;
        A4[j] = vv;
    }
}

// Full-grid scatter: max TLP for the 1.6M atomics + scattered stores.
__global__ void k_scatter(const int* __restrict__ esrc, const int* __restrict__ edst, int e) {
    int i = blockIdx.x * blockDim.x + threadIdx.x;
    if (i < e) {
        int p = atomicAdd(&g_cursor[edst[i]], 1);
        g_csrc[p] = esrc[i];
    }
}

// agg pass 1 fused with cheb1. Warp per node; 4 groups of 8 lanes, group =
// edge. Plain counted loop — measured fastest form.
__global__ void k_aggcheb(const float* __restrict__ u, const float* __restrict__ lam, int n) {
    int w = (blockIdx.x * blockDim.x + threadIdx.x) >> 5;
    int lane = threadIdx.x & 31;
    if (w >= n) return;
    int grp = lane >> 3, sub = lane & 7;
    int s0 = g_rowptr[w], s1 = g_rowptr[w + 1];
    const float4* A4 = (const float4*)g_A;
    float4 acc = make_float4(0.f, 0.f, 0.f, 0.f);
    for (int e = s0 + grp; e < s1; e += 4) {
        int sid = g_csrc[e];
        float4 v = A4[sid * 8 + sub];
        acc.x += v.x; acc.y += v.y; acc.z += v.z; acc.w += v.w;
    }
    // all lanes reconverged: full-warp shuffles safe
#pragma unroll
    for (int off = 8; off <= 16; off <<= 1) {
        acc.x += __shfl_xor_sync(0xffffffffu, acc.x, off);
        acc.y += __shfl_xor_sync(0xffffffffu, acc.y, off);
        acc.z += __shfl_xor_sync(0xffffffffu, acc.z, off);
        acc.w += __shfl_xor_sync(0xffffffffu, acc.w, off);
    }
    if (grp == 0) {
        float d = g_Dinv[w];
        float r = 2.0f / lam[0];
        float4 uv = ((const float4*)u)[w * 8 + sub];
        float4 x1;
        x1.x = -r * (acc.x * d) + (r - 1.0f) * uv.x;
        x1.y = -r * (acc.y * d) + (r - 1.0f) * uv.y;
        x1.z = -r * (acc.z * d) + (r - 1.0f) * uv.z;
        x1.w = -r * (acc.w * d) + (r - 1.0f) * uv.w;
        ((float4*)g_X1)[w * 8 + sub] = x1;
        float4 a; a.x = x1.x * d; a.y = x1.y * d; a.z = x1.z * d; a.w = x1.w * d;
        ((float4*)g_A2)[w * 8 + sub] = a;
    }
}

// agg pass 2 fused with node GEMMs (R14 monolith — measured-best config:
// wall-clock beats the split variant; ncu's "147us" was cold-L2 inflation).
// 1024-thread blocks = 32 nodes/block so smem weights load 4x less often.
__global__ __launch_bounds__(1024, 1)
void k_aggnode(const float* __restrict__ u, const float* __restrict__ lam,
               const float* __restrict__ Wc, const float* __restrict__ bc,
               const float* __restrict__ Ws, const float* __restrict__ bs,
               const float* __restrict__ Wd, const float* __restrict__ bd,
               int n) {
    __shared__ __align__(16) float sW1t[32 * 100];
    __shared__ __align__(16) float sW2t[32 * 36];
    __shared__ __align__(16) float sW3t[32 * 36];
    __shared__ float sb1[32], sb2[32], sb3[32];
    __shared__ __align__(16) float xsh[32][96];
    __shared__ __align__(16) float hcsh[32][32];

    int tid = threadIdx.x;
    for (int i = tid; i < 96 * 32; i += 1024) {
        int j = i >> 5, d = i & 31;
        sW1t[d * 100 + j] = Wc[i];
    }
    for (int i = tid; i < 32 * 32; i += 1024) {
        int j = i >> 5, d = i & 31;
        sW2t[d * 36 + j] = Ws[i];
        sW3t[d * 36 + j] = Wd[i];
    }
    if (tid < 32) { sb1[tid] = bc[tid]; sb2[tid] = bs[tid]; sb3[tid] = bd[tid]; }
    __syncthreads();

    int wid = tid >> 5, lane = tid & 31;
    int node = blockIdx.x * 32 + wid;
    if (node >= n) return;
    int grp = lane >> 3, sub = lane & 7;

    int s0 = g_rowptr[node], s1 = g_rowptr[node + 1];
    const float4* A4 = (const float4*)g_A2;
    float4 acc = make_float4(0.f, 0.f, 0.f, 0.f);
    for (int e = s0 + grp; e < s1; e += 4) {
        int sid = g_csrc[e];
        float4 v = A4[sid * 8 + sub];
        acc.x += v.x; acc.y += v.y; acc.z += v.z; acc.w += v.w;
    }
#pragma unroll
    for (int off = 8; off <= 16; off <<= 1) {
        acc.x += __shfl_xor_sync(0xffffffffu, acc.x, off);
        acc.y += __shfl_xor_sync(0xffffffffu, acc.y, off);
        acc.z += __shfl_xor_sync(0xffffffffu, acc.z, off);
        acc.w += __shfl_xor_sync(0xffffffffu, acc.w, off);
    }
    if (grp == 0) {
        float d = g_Dinv[node];
        float r = 2.0f / lam[0];
        float4 uv = ((const float4*)u)[node * 8 + sub];
        float4 x1 = ((const float4*)g_X1)[node * 8 + sub];
        float4 x2;
        x2.x = -2.0f * r * (acc.x * d) + 2.0f * (r - 1.0f) * x1.x - uv.x;
        x2.y = -2.0f * r * (acc.y * d) + 2.0f * (r - 1.0f) * x1.y - uv.y;
        x2.z = -2.0f * r * (acc.z * d) + 2.0f * (r - 1.0f) * x1.z - uv.z;
        x2.w = -2.0f * r * (acc.w * d) + 2.0f * (r - 1.0f) * x1.w - uv.w;
        ((float4*)&xsh[wid][0])[sub] = uv;
        ((float4*)&xsh[wid][32])[sub] = x1;
        ((float4*)&xsh[wid][64])[sub] = x2;
    }
    __syncwarp();

    float acc1s = sb1[lane];
    const float4* xr = (const float4*)&xsh[wid][0];
    const float4* w1 = (const float4*)&sW1t[lane * 100];
#pragma unroll
    for (int j4 = 0; j4 < 24; j4++) {
        float4 xv = xr[j4];
        float4 wv = w1[j4];
        acc1s += xv.x * wv.x + xv.y * wv.y + xv.z * wv.z + xv.w * wv.w;
    }
    float hc = fmaxf(acc1s, 0.0f);
    hcsh[wid][lane] = hc;
    __syncwarp();

    float fs = sb2[lane], fd = sb3[lane];
    const float4* hr = (const float4*)&hcsh[wid][0];
    const float4* w2 = (const float4*)&sW2t[lane * 36];
    const float4* w3 = (const float4*)&sW3t[lane * 36];
#pragma unroll
    for (int j4 = 0; j4 < 8; j4++) {
        float4 hv = hr[j4];
        float4 a2 = w2[j4];
        float4 a3 = w3[j4];
        fs += hv.x * a2.x + hv.y * a2.y + hv.z * a2.z + hv.w * a2.w;
        fd += hv.x * a3.x + hv.y * a3.y + hv.z * a3.z + hv.w * a3.w;
    }
    g_FS[node * DIM + lane] = fs;
    g_FD[node * DIM + lane] = fd;
}

// GATv2 fused edge softmax + aggregation (no max subtraction; logits bounded
// ~13 -> exp safe in fp32). exp2f trick: attn vector pre-scaled by log2(e) so
// the per-edge exponent is a single MUFU.EX2 (saves the __expf internal mul).
// Group-mask shuffles in the divergent loop; full mask after. Re-zeroes g_deg.
__global__ __launch_bounds__(256, 7)
void k_attn(float* __restrict__ out, const float* __restrict__ attn, int n) {
    int gid = blockIdx.x * blockDim.x + threadIdx.x;
    if (gid < NN) g_deg[gid] = 0;          // restore call-entry invariant
    int w = gid >> 5;
    int lane = threadIdx.x & 31;
    if (w >= n) return;
    int grp = lane >> 3, sub = lane & 7;
    unsigned gmask = 0xffu << (grp * 8);
    int s0 = g_rowptr[w], s1 = g_rowptr[w + 1];
    const float4* FS4 = (const float4*)g_FS;
    float4 a4 = ((const float4*)attn)[sub];
    a4.x *= LOG2E; a4.y *= LOG2E; a4.z *= LOG2E; a4.w *= LOG2E;
    float4 fd4 = ((const float4*)g_FD)[w * 8 + sub];

    float den = 0.0f;
    float4 acc = make_float4(0.f, 0.f, 0.f, 0.f);

    for (int e = s0 + grp; e < s1; e += 4) {
        int sid = g_csrc[e];
        float4 v = FS4[sid * 8 + sub];
        float4 t;
        t.x = v.x + fd4.x; t.y = v.y + fd4.y; t.z = v.z + fd4.z; t.w = v.w + fd4.w;
        t.x = (t.x > 0.f) ? t.x : NEG_SLOPE * t.x;
        t.y = (t.y > 0.f) ? t.y : NEG_SLOPE * t.y;
        t.z = (t.z > 0.f) ? t.z : NEG_SLOPE * t.z;
        t.w = (t.w > 0.f) ? t.w : NEG_SLOPE * t.w;
        float l = t.x * a4.x + t.y * a4.y + t.z * a4.z + t.w * a4.w;
#pragma unroll
        for (int off = 1; off <= 4; off <<= 1)
            l += __shfl_xor_sync(gmask, l, off);   // group-local, converged
        float p = exp2f(l);                        // l already includes log2e
        den += p;
        acc.x += p * v.x; acc.y += p * v.y; acc.z += p * v.z; acc.w += p * v.w;
    }

    // merge the 4 group partial sums (all lanes reconverged -> full mask ok)
#pragma unroll
    for (int off = 8; off <= 16; off <<= 1) {
        den   += __shfl_xor_sync(0xffffffffu, den, off);
        acc.x += __shfl_xor_sync(0xffffffffu, acc.x, off);
        acc.y += __shfl_xor_sync(0xffffffffu, acc.y, off);
        acc.z += __shfl_xor_sync(0xffffffffu, acc.z, off);
        acc.w += __shfl_xor_sync(0xffffffffu, acc.w, off);
    }

    if (grp == 0) {
        float4 o;
        if (den > 0.0f) {
            float inv = 1.0f / den;
            o.x = acc.x * inv; o.y = acc.y * inv; o.z = acc.z * inv; o.w = acc.w * inv;
        } else {
            o = make_float4(0.f, 0.f, 0.f, 0.f);
        }
        ((float4*)out)[w * 8 + sub] = o;
    }
}

// ---------------------------------------------------------------------
extern "C" void kernel_launch(void* const* d_in, const int* in_sizes, int n_in,
                              void* d_out, int out_size) {
    const float* u     = (const float*)d_in[0];
    const float* lam   = (const float*)d_in[1];
    const int*   esrc  = (const int*)d_in[2];
    const int*   edst  = (const int*)d_in[3];
    const float* chebW = (const float*)d_in[4];
    const float* chebb = (const float*)d_in[5];
    const float* srcW  = (const float*)d_in[6];
    const float* srcb  = (const float*)d_in[7];
    const float* dstW  = (const float*)d_in[8];
    const float* dstb  = (const float*)d_in[9];
    const float* attn  = (const float*)d_in[10];
    float* out = (float*)d_out;

    int N = in_sizes[0] / DIM;
    int E = in_sizes[2];

    int tb = 256;
    int gE = (E + tb - 1) / tb;
    int gWarp = (N * 32 + tb - 1) / tb;
    int gNode32 = (N + 31) / 32;

    k_histscan<<<CSR_BLOCKS, CSR_THREADS>>>(u, edst, N, E);   // 0
    k_scatter<<<gE, tb>>>(esrc, edst, E);                     // 1
    k_aggcheb<<<gWarp, tb>>>(u, lam, N);                      // 2
    k_aggnode<<<gNode32, 1024>>>(u, lam, chebW, chebb,
                                 srcW, srcb, dstW, dstb, N);  // 3
    k_attn<<<gWarp, tb>>>(out, attn, N);                      // 4
}

// round 17
// speedup vs baseline: 1.3204x; 1.2585x over previous
#include <cuda_runtime.h>
#include <cuda_bf16.h>
#include <float.h>

#define NN 100000
#define NE 1600000
#define DIM 32
#define NEG_SLOPE 0.2f
#define LOG2E 1.44269504f
#define CSR_BLOCKS 148
#define CSR_THREADS 1024

// -------- static device scratch (16B aligned for float4 access) --------
// Invariant: g_deg == 0 at every kernel_launch entry (zero at module load,
// re-zeroed by k_attn each call). Barrier cnt returns to 0 after each use.
__device__ int      g_deg[NN];
__device__ int      g_cursor[NN];
__device__ int      g_rowptr[NN + 1];
__device__ int      g_partial[CSR_BLOCKS];
__device__ unsigned g_bar_cnt = 0;
__device__ unsigned g_bar_gen = 0;
__device__ int      g_csrc[NE];                    // src ids grouped by dst (CSR)
__device__ float    g_Dinv[NN];
__device__ __align__(16) float g_A[NN * DIM];      // pass-1 agg input (u*Dinv)
__device__ __align__(16) float g_A2[NN * DIM];     // pass-2 agg input (X1*Dinv)
__device__ __align__(16) float g_X1[NN * DIM];
__device__ __align__(16) float g_FS[NN * DIM];     // fsrc
__device__ __align__(16) float g_FD[NN * DIM];     // fdst

// Sense-reversing grid barrier (all CSR_BLOCKS co-resident: 148 <= 152 SMs).
__device__ __forceinline__ void grid_bar() {
    __syncthreads();
    if (threadIdx.x == 0) {
        __threadfence();
        unsigned gen = *(volatile unsigned*)&g_bar_gen;
        unsigned a = atomicAdd(&g_bar_cnt, 1u);
        if (a == gridDim.x - 1) {
            *(volatile unsigned*)&g_bar_cnt = 0;
            __threadfence();
            atomicAdd(&g_bar_gen, 1u);            // release
        } else {
            while (*(volatile unsigned*)&g_bar_gen == gen) __nanosleep(64);
        }
        __threadfence();
    }
    __syncthreads();
}

// Block-wide exclusive scan over 1024 threads. Returns (exclusive, total).
__device__ __forceinline__ int2 block_scan(int v, int* swarp) {
    int lane = threadIdx.x & 31, w5 = threadIdx.x >> 5;
    int x = v;
#pragma unroll
    for (int off = 1; off < 32; off <<= 1) {
        int y = __shfl_up_sync(0xffffffffu, x, off);
        if (lane >= off) x += y;
    }
    if (lane == 31) swarp[w5] = x;
    __syncthreads();
    if (w5 == 0) {
        int s = swarp[lane];
#pragma unroll
        for (int off = 1; off < 32; off <<= 1) {
            int y = __shfl_up_sync(0xffffffffu, s, off);
            if (lane >= off) s += y;
        }
        swarp[lane] = s;
    }
    __syncthreads();
    int incl = x + (w5 > 0 ? swarp[w5 - 1] : 0);
    int total = swarp[31];
    __syncthreads();                               // protect smem reuse
    return make_int2(incl - v, total);
}

// Persistent: histogram -> scan -> rowptr/cursor/Dinv -> A = u*Dinv.
__global__ __launch_bounds__(CSR_THREADS, 1)
void k_histscan(const float* __restrict__ u, const int* __restrict__ edst,
                int n, int e) {
    __shared__ int swarp[32];
    int tid = threadIdx.x, bid = blockIdx.x;
    int gt = bid * CSR_THREADS + tid;
    int gsz = gridDim.x * CSR_THREADS;

    for (int i = gt; i < e; i += gsz)
        atomicAdd(&g_deg[edst[i]], 1);
    grid_bar();

    int node = gt;
    int v = (node < n) ? g_deg[node] : 0;
    int2 sc = block_scan(v, swarp);
    if (tid == 0) g_partial[bid] = sc.y;
    grid_bar();

    if (bid == 0) {
        int vv = (tid < CSR_BLOCKS) ? g_partial[tid] : 0;
        int2 sc2 = block_scan(vv, swarp);
        if (tid < CSR_BLOCKS) g_partial[tid] = sc2.x;
        if (tid == CSR_BLOCKS - 1) g_rowptr[n] = sc2.x + vv;   // grand total
    }
    grid_bar();

    if (node < n) {
        int off = g_partial[bid] + sc.x;
        g_rowptr[node] = off;
        g_cursor[node] = off;
        float dg = (float)v;
        g_Dinv[node] = rsqrtf(dg < 1.0f ? 1.0f : dg);
    }
    grid_bar();

    const float4* u4 = (const float4*)u;
    float4* A4 = (float4*)g_A;
    int n8 = n * 8;
    for (int j = gt; j < n8; j += gsz) {
        float d = g_Dinv[j >> 3];
        float4 vv = u4[j];
        vv.x *= d; vv.y *= d; vv.z *= d; vv.w *= d;
        A4[j] = vv;
    }
}

// Full-grid scatter: max TLP for the 1.6M atomics + scattered stores.
__global__ void k_scatter(const int* __restrict__ esrc, const int* __restrict__ edst, int e) {
    int i = blockIdx.x * blockDim.x + threadIdx.x;
    if (i < e) {
        int p = atomicAdd(&g_cursor[edst[i]], 1);
        g_csrc[p] = esrc[i];
    }
}

// agg pass 1 fused with cheb1. Warp per node; 4 groups of 8 lanes, group =
// edge. Plain counted loop — measured fastest form.
__global__ void k_aggcheb(const float* __restrict__ u, const float* __restrict__ lam, int n) {
    int w = (blockIdx.x * blockDim.x + threadIdx.x) >> 5;
    int lane = threadIdx.x & 31;
    if (w >= n) return;
    int grp = lane >> 3, sub = lane & 7;
    int s0 = g_rowptr[w], s1 = g_rowptr[w + 1];
    const float4* A4 = (const float4*)g_A;
    float4 acc = make_float4(0.f, 0.f, 0.f, 0.f);
    for (int e = s0 + grp; e < s1; e += 4) {
        int sid = g_csrc[e];
        float4 v = A4[sid * 8 + sub];
        acc.x += v.x; acc.y += v.y; acc.z += v.z; acc.w += v.w;
    }
    // all lanes reconverged: full-warp shuffles safe
#pragma unroll
    for (int off = 8; off <= 16; off <<= 1) {
        acc.x += __shfl_xor_sync(0xffffffffu, acc.x, off);
        acc.y += __shfl_xor_sync(0xffffffffu, acc.y, off);
        acc.z += __shfl_xor_sync(0xffffffffu, acc.z, off);
        acc.w += __shfl_xor_sync(0xffffffffu, acc.w, off);
    }
    if (grp == 0) {
        float d = g_Dinv[w];
        float r = 2.0f / lam[0];
        float4 uv = ((const float4*)u)[w * 8 + sub];
        float4 x1;
        x1.x = -r * (acc.x * d) + (r - 1.0f) * uv.x;
        x1.y = -r * (acc.y * d) + (r - 1.0f) * uv.y;
        x1.z = -r * (acc.z * d) + (r - 1.0f) * uv.z;
        x1.w = -r * (acc.w * d) + (r - 1.0f) * uv.w;
        ((float4*)g_X1)[w * 8 + sub] = x1;
        float4 a; a.x = x1.x * d; a.y = x1.y * d; a.z = x1.z * d; a.w = x1.w * d;
        ((float4*)g_A2)[w * 8 + sub] = a;
    }
}

// agg pass 2 fused with node GEMMs. KEY CHANGE vs R14: each warp now owns
// FOUR nodes, so each weight float4 read from smem is applied to 4 nodes'
// features (x side is broadcast-LDS, ~free). Crossbar cost per node drops
// ~200 -> ~75 cyc; the profile showed L1(shared)=66.5% busy = the bottleneck.
// 512 threads / 64 nodes per block; smem 47KB (<48KB static limit);
// launch_bounds(512,2) -> 2 blocks/SM (32 warps, regs capped at 64).
__global__ __launch_bounds__(512, 2)
void k_aggnode(const float* __restrict__ u, const float* __restrict__ lam,
               const float* __restrict__ Wc, const float* __restrict__ bc,
               const float* __restrict__ Ws, const float* __restrict__ bs,
               const float* __restrict__ Wd, const float* __restrict__ bd,
               int n) {
    __shared__ __align__(16) float sW1t[32 * 100];   // Wc^T, stride 100
    __shared__ __align__(16) float sW2t[32 * 36];    // Ws^T, stride 36
    __shared__ __align__(16) float sW3t[32 * 36];    // Wd^T, stride 36
    __shared__ float sb1[32], sb2[32], sb3[32];
    __shared__ __align__(16) float xsh[64][96];      // [node_in_block][feature]

    int tid = threadIdx.x;
    for (int i = tid; i < 96 * 32; i += 512) {
        int j = i >> 5, d = i & 31;
        sW1t[d * 100 + j] = Wc[i];
    }
    for (int i = tid; i < 32 * 32; i += 512) {
        int j = i >> 5, d = i & 31;
        sW2t[d * 36 + j] = Ws[i];
        sW3t[d * 36 + j] = Wd[i];
    }
    if (tid < 32) { sb1[tid] = bc[tid]; sb2[tid] = bs[tid]; sb3[tid] = bd[tid]; }
    __syncthreads();

    int wid = tid >> 5, lane = tid & 31;
    int grp = lane >> 3, sub = lane & 7;
    int row0 = wid * 4;                       // this warp's 4 xsh rows
    int nb = blockIdx.x * 64 + row0;          // first of this warp's 4 nodes
    const float4* A4 = (const float4*)g_A2;
    float r = 2.0f / lam[0];

    // ---- gather + X2 for 4 nodes (sequential; 4 groups x 8 lanes each) ----
#pragma unroll
    for (int m = 0; m < 4; m++) {
        int node = nb + m;
        if (node >= n) break;                 // uniform across warp
        int s0 = g_rowptr[node], s1 = g_rowptr[node + 1];
        float4 acc = make_float4(0.f, 0.f, 0.f, 0.f);
        for (int e = s0 + grp; e < s1; e += 4) {
            int sid = g_csrc[e];
            float4 v = A4[sid * 8 + sub];
            acc.x += v.x; acc.y += v.y; acc.z += v.z; acc.w += v.w;
        }
#pragma unroll
        for (int off = 8; off <= 16; off <<= 1) {
            acc.x += __shfl_xor_sync(0xffffffffu, acc.x, off);
            acc.y += __shfl_xor_sync(0xffffffffu, acc.y, off);
            acc.z += __shfl_xor_sync(0xffffffffu, acc.z, off);
            acc.w += __shfl_xor_sync(0xffffffffu, acc.w, off);
        }
        if (grp == 0) {
            float d = g_Dinv[node];
            float4 uv = ((const float4*)u)[node * 8 + sub];
            float4 x1 = ((const float4*)g_X1)[node * 8 + sub];
            float4 x2;
            x2.x = -2.0f * r * (acc.x * d) + 2.0f * (r - 1.0f) * x1.x - uv.x;
            x2.y = -2.0f * r * (acc.y * d) + 2.0f * (r - 1.0f) * x1.y - uv.y;
            x2.z = -2.0f * r * (acc.z * d) + 2.0f * (r - 1.0f) * x1.z - uv.z;
            x2.w = -2.0f * r * (acc.w * d) + 2.0f * (r - 1.0f) * x1.w - uv.w;
            ((float4*)&xsh[row0 + m][0])[sub] = uv;
            ((float4*)&xsh[row0 + m][32])[sub] = x1;
            ((float4*)&xsh[row0 + m][64])[sub] = x2;
        }
    }
    __syncwarp();

    // ---- GEMM1: hc = relu([X0|X1|X2]@Wc + bc), 4 nodes per weight read ----
    float a0 = sb1[lane], a1 = a0, a2 = a0, a3 = a0;
    const float4* w1 = (const float4*)&sW1t[lane * 100];
    const float4* x0p = (const float4*)&xsh[row0 + 0][0];
    const float4* x1p = (const float4*)&xsh[row0 + 1][0];
    const float4* x2p = (const float4*)&xsh[row0 + 2][0];
    const float4* x3p = (const float4*)&xsh[row0 + 3][0];
#pragma unroll
    for (int j4 = 0; j4 < 24; j4++) {
        float4 wv = w1[j4];
        float4 v0 = x0p[j4], v1 = x1p[j4], v2 = x2p[j4], v3 = x3p[j4];
        a0 += v0.x * wv.x + v0.y * wv.y + v0.z * wv.z + v0.w * wv.w;
        a1 += v1.x * wv.x + v1.y * wv.y + v1.z * wv.z + v1.w * wv.w;
        a2 += v2.x * wv.x + v2.y * wv.y + v2.z * wv.z + v2.w * wv.w;
        a3 += v3.x * wv.x + v3.y * wv.y + v3.z * wv.z + v3.w * wv.w;
    }
    __syncwarp();
    // X consumed; reuse xsh[row][0..31] for hc
    xsh[row0 + 0][lane] = fmaxf(a0, 0.0f);
    xsh[row0 + 1][lane] = fmaxf(a1, 0.0f);
    xsh[row0 + 2][lane] = fmaxf(a2, 0.0f);
    xsh[row0 + 3][lane] = fmaxf(a3, 0.0f);
    __syncwarp();

    // ---- GEMM2/3: FS = hc@Ws + bs ; FD = hc@Wd + bd ----
    float fs0 = sb2[lane], fs1 = fs0, fs2 = fs0, fs3 = fs0;
    float fd0 = sb3[lane], fd1 = fd0, fd2 = fd0, fd3 = fd0;
    const float4* w2 = (const float4*)&sW2t[lane * 36];
    const float4* w3 = (const float4*)&sW3t[lane * 36];
#pragma unroll
    for (int j4 = 0; j4 < 8; j4++) {
        float4 wa = w2[j4];
        float4 wb = w3[j4];
        float4 h0 = x0p[j4], h1 = x1p[j4], h2 = x2p[j4], h3 = x3p[j4];
        fs0 += h0.x * wa.x + h0.y * wa.y + h0.z * wa.z + h0.w * wa.w;
        fs1 += h1.x * wa.x + h1.y * wa.y + h1.z * wa.z + h1.w * wa.w;
        fs2 += h2.x * wa.x + h2.y * wa.y + h2.z * wa.z + h2.w * wa.w;
        fs3 += h3.x * wa.x + h3.y * wa.y + h3.z * wa.z + h3.w * wa.w;
        fd0 += h0.x * wb.x + h0.y * wb.y + h0.z * wb.z + h0.w * wb.w;
        fd1 += h1.x * wb.x + h1.y * wb.y + h1.z * wb.z + h1.w * wb.w;
        fd2 += h2.x * wb.x + h2.y * wb.y + h2.z * wb.z + h2.w * wb.w;
        fd3 += h3.x * wb.x + h3.y * wb.y + h3.z * wb.z + h3.w * wb.w;
    }
    if (nb + 0 < n) { g_FS[(nb + 0) * DIM + lane] = fs0; g_FD[(nb + 0) * DIM + lane] = fd0; }
    if (nb + 1 < n) { g_FS[(nb + 1) * DIM + lane] = fs1; g_FD[(nb + 1) * DIM + lane] = fd1; }
    if (nb + 2 < n) { g_FS[(nb + 2) * DIM + lane] = fs2; g_FD[(nb + 2) * DIM + lane] = fd2; }
    if (nb + 3 < n) { g_FS[(nb + 3) * DIM + lane] = fs3; g_FD[(nb + 3) * DIM + lane] = fd3; }
}

// GATv2 fused edge softmax + aggregation (no max subtraction; logits bounded
// ~13 -> exp safe in fp32). exp2f: attn pre-scaled by log2(e). Group-mask
// shuffles in the divergent loop; full mask after. Re-zeroes g_deg.
__global__ __launch_bounds__(256, 7)
void k_attn(float* __restrict__ out, const float* __restrict__ attn, int n) {
    int gid = blockIdx.x * blockDim.x + threadIdx.x;
    if (gid < NN) g_deg[gid] = 0;          // restore call-entry invariant
    int w = gid >> 5;
    int lane = threadIdx.x & 31;
    if (w >= n) return;
    int grp = lane >> 3, sub = lane & 7;
    unsigned gmask = 0xffu << (grp * 8);
    int s0 = g_rowptr[w], s1 = g_rowptr[w + 1];
    const float4* FS4 = (const float4*)g_FS;
    float4 a4 = ((const float4*)attn)[sub];
    a4.x *= LOG2E; a4.y *= LOG2E; a4.z *= LOG2E; a4.w *= LOG2E;
    float4 fd4 = ((const float4*)g_FD)[w * 8 + sub];

    float den = 0.0f;
    float4 acc = make_float4(0.f, 0.f, 0.f, 0.f);

    for (int e = s0 + grp; e < s1; e += 4) {
        int sid = g_csrc[e];
        float4 v = FS4[sid * 8 + sub];
        float4 t;
        t.x = v.x + fd4.x; t.y = v.y + fd4.y; t.z = v.z + fd4.z; t.w = v.w + fd4.w;
        t.x = (t.x > 0.f) ? t.x : NEG_SLOPE * t.x;
        t.y = (t.y > 0.f) ? t.y : NEG_SLOPE * t.y;
        t.z = (t.z > 0.f) ? t.z : NEG_SLOPE * t.z;
        t.w = (t.w > 0.f) ? t.w : NEG_SLOPE * t.w;
        float l = t.x * a4.x + t.y * a4.y + t.z * a4.z + t.w * a4.w;
#pragma unroll
        for (int off = 1; off <= 4; off <<= 1)
            l += __shfl_xor_sync(gmask, l, off);   // group-local, converged
        float p = exp2f(l);                        // l already includes log2e
        den += p;
        acc.x += p * v.x; acc.y += p * v.y; acc.z += p * v.z; acc.w += p * v.w;
    }

    // merge the 4 group partial sums (all lanes reconverged -> full mask ok)
#pragma unroll
    for (int off = 8; off <= 16; off <<= 1) {
        den   += __shfl_xor_sync(0xffffffffu, den, off);
        acc.x += __shfl_xor_sync(0xffffffffu, acc.x, off);
        acc.y += __shfl_xor_sync(0xffffffffu, acc.y, off);
        acc.z += __shfl_xor_sync(0xffffffffu, acc.z, off);
        acc.w += __shfl_xor_sync(0xffffffffu, acc.w, off);
    }

    if (grp == 0) {
        float4 o;
        if (den > 0.0f) {
            float inv = 1.0f / den;
            o.x = acc.x * inv; o.y = acc.y * inv; o.z = acc.z * inv; o.w = acc.w * inv;
        } else {
            o = make_float4(0.f, 0.f, 0.f, 0.f);
        }
        ((float4*)out)[w * 8 + sub] = o;
    }
}

// ---------------------------------------------------------------------
extern "C" void kernel_launch(void* const* d_in, const int* in_sizes, int n_in,
                              void* d_out, int out_size) {
    const float* u     = (const float*)d_in[0];
    const float* lam   = (const float*)d_in[1];
    const int*   esrc  = (const int*)d_in[2];
    const int*   edst  = (const int*)d_in[3];
    const float* chebW = (const float*)d_in[4];
    const float* chebb = (const float*)d_in[5];
    const float* srcW  = (const float*)d_in[6];
    const float* srcb  = (const float*)d_in[7];
    const float* dstW  = (const float*)d_in[8];
    const float* dstb  = (const float*)d_in[9];
    const float* attn  = (const float*)d_in[10];
    float* out = (float*)d_out;

    int N = in_sizes[0] / DIM;
    int E = in_sizes[2];

    int tb = 256;
    int gE = (E + tb - 1) / tb;
    int gWarp = (N * 32 + tb - 1) / tb;
    int gNode64 = (N + 63) / 64;

    k_histscan<<<CSR_BLOCKS, CSR_THREADS>>>(u, edst, N, E);   // 0
    k_scatter<<<gE, tb>>>(esrc, edst, E);                     // 1
    k_aggcheb<<<gWarp, tb>>>(u, lam, N);                      // 2
    k_aggnode<<<gNode64, 512>>>(u, lam, chebW, chebb,
                                srcW, srcb, dstW, dstb, N);   // 3  <- ncu lands here
    k_attn<<<gWarp, tb>>>(out, attn, N);                      // 4
}